// round 12
// baseline (speedup 1.0000x reference)
#include <cuda_runtime.h>

#define WIDTH   512
#define HEIGHT  512
#define TH      8                  // output rows per CTA
#define NTH     256                // threads per CTA
// 8B tuple per pixel; +8B pad every 8 tuples; +32B low-halo head; 3 high-halo
// tuples at the tail. tuple x at byte 32 + 8x + 8(x>>3); max 4656+8 -> 4672.
#define TROWB   4672
#define SMEM_BYTES (TH * TROWB)    // 37376

typedef unsigned long long u64;

__device__ __forceinline__ int refl(int i, int n) {
    i = i < 0 ? -i : i;
    return i >= n ? 2 * n - 2 - i : i;
}
__device__ __forceinline__ u64 pack2(float lo, float hi) {
    u64 r; asm("mov.b64 %0, {%1, %2};" : "=l"(r) : "f"(lo), "f"(hi)); return r;
}
__device__ __forceinline__ void unpack2(u64 v, float& lo, float& hi) {
    asm("mov.b64 {%0, %1}, %2;" : "=f"(lo), "=f"(hi) : "l"(v));
}
__device__ __forceinline__ u64 fma2(u64 a, u64 b, u64 c) {   // FFMA2
    u64 d; asm("fma.rn.f32x2 %0, %1, %2, %3;" : "=l"(d) : "l"(a), "l"(b), "l"(c));
    return d;
}
__device__ __forceinline__ float frsq_ap(float x) {
    float r; asm("rsqrt.approx.f32 %0, %1;" : "=f"(r) : "f"(x)); return r;
}

// Stage-1 vertical 7-tap blur of ONE tensor, one column; writes packed
// (mean, E2) u64 per output row into the padded tuple layout, duplicating
// reflected x-halos. EDGE=false: immediate-offset LDGs, zero per-row ALU.
template<bool EDGE>
__device__ __forceinline__ void stage1_col(const float* __restrict__ p,
                                           unsigned char* sm,
                                           int x, int y0, const u64* G2) {
    const unsigned sbase = (unsigned)(32 + 8 * x + 8 * (x >> 3));
    int hs = -1;                                   // halo duplicate byte
    if (x >= 1 && x <= 3)      hs = 24 - 8 * x;    // 16,8,0   (x -> -x)
    if (x >= 508 && x <= 510)  hs = 8720 - 8 * x;  // 4656,4648,4640

    u64 r[7];                                      // ring: packed (v, v^2)
    const float* base = p + (y0 - 3) * WIDTH + x;  // valid when !EDGE
    #pragma unroll
    for (int i = 0; i < TH + 6; ++i) {
        float v;
        if (EDGE) v = __ldg(p + refl(y0 - 3 + i, HEIGHT) * WIDTH + x);
        else      v = __ldg(base + i * WIDTH);     // LDG [R + imm]
        r[i % 7] = pack2(v, v * v);
        if (i >= 6) {
            const int o = i - 6;                   // output row within tile
            u64 a = 0ull;
            #pragma unroll
            for (int k = 0; k < 7; ++k)
                a = fma2(G2[k], r[(o + k) % 7], a);
            *reinterpret_cast<u64*>(sm + o * TROWB + sbase) = a;
            if (hs >= 0)
                *reinterpret_cast<u64*>(sm + o * TROWB + hs) = a;
        }
    }
}

// Horizontal 7-tap blur: 14 immediate-offset LDS.64 -> 8 packed accumulators.
__device__ __forceinline__ void hblur(const unsigned char* smrow,
                                      const u64* G2, u64* acc) {
    #pragma unroll
    for (int o = 0; o < 8; ++o) acc[o] = 0ull;
    #pragma unroll
    for (int j = 0; j < 14; ++j) {
        const int off = 8 * j + ((j < 3) ? 0 : (j < 11) ? 8 : 16);
        const u64 w = *reinterpret_cast<const u64*>(smrow + off);
        #pragma unroll
        for (int o = 0; o < 8; ++o) {
            const int k = j - o;
            if (k >= 0 && k < 7)                   // compile-time predicate
                acc[o] = fma2(G2[k], w, acc[o]);
        }
    }
}

__global__ __launch_bounds__(NTH, 4)
void adain_local_kernel(const float* __restrict__ content,
                        const float* __restrict__ style,
                        float* __restrict__ out) {
    extern __shared__ unsigned char sm[];

    const float G[7] = {0.0044330481752437f, 0.0540055826224143f,
                        0.2420362293761143f, 0.3990502746173879f,
                        0.2420362293761143f, 0.0540055826224143f,
                        0.0044330481752437f};
    u64 G2[7];
    #pragma unroll
    for (int k = 0; k < 7; ++k) G2[k] = pack2(G[k], G[k]);

    const int plane = blockIdx.y;
    const int y0    = blockIdx.x * TH;
    const size_t pb = (size_t)plane * (WIDTH * HEIGHT);
    const float* cp = content + pb;
    const float* sp = style   + pb;
    float*       op = out     + pb;
    const int tid = threadIdx.x;
    const bool interior = (y0 >= 3) && (y0 + TH + 3 <= HEIGHT);

    // stage-2 task geometry (2 tasks per thread), shared by both passes
    const int row0 = tid >> 6,        l0 = tid & 63;
    const int row1 = (tid + NTH) >> 6, l1 = (tid + NTH) & 63;
    const unsigned char* smr0 = sm + row0 * TROWB + 72 * l0;
    const unsigned char* smr1 = sm + row1 * TROWB + 72 * l1;

    float normed[16];                   // (craw - cm) / cstd for 2 tasks

    // ================= CONTENT PASS =================
    if (interior) {
        stage1_col<false>(cp, sm, tid,       y0, G2);
        stage1_col<false>(cp, sm, tid + NTH, y0, G2);
    } else {
        stage1_col<true >(cp, sm, tid,       y0, G2);
        stage1_col<true >(cp, sm, tid + NTH, y0, G2);
    }
    __syncthreads();

    #pragma unroll
    for (int t = 0; t < 2; ++t) {
        const int gy = y0 + (t ? row1 : row0);
        const int xc = (t ? l1 : l0) << 3;
        const float4 cA = *reinterpret_cast<const float4*>(cp + gy * WIDTH + xc);
        const float4 cB = *reinterpret_cast<const float4*>(cp + gy * WIDTH + xc + 4);
        u64 acc[8];
        hblur(t ? smr1 : smr0, G2, acc);
        const float craw[8] = {cA.x, cA.y, cA.z, cA.w, cB.x, cB.y, cB.z, cB.w};
        #pragma unroll
        for (int o = 0; o < 8; ++o) {
            float cm, cE2;
            unpack2(acc[o], cm, cE2);
            const float cv  = fmaxf(fmaf(-cm, cm, cE2), 1e-6f);
            const float rqc = frsq_ap(cv);                  // MUFU.RSQ
            const float dinv = rqc - (1e-5f * rqc) * rqc;   // ~1/(sqrt(cv)+eps)
            normed[t * 8 + o] = (craw[o] - cm) * dinv;
        }
    }
    __syncthreads();     // all stage-2 reads done before style overwrites smem

    // ================= STYLE PASS =================
    if (interior) {
        stage1_col<false>(sp, sm, tid,       y0, G2);
        stage1_col<false>(sp, sm, tid + NTH, y0, G2);
    } else {
        stage1_col<true >(sp, sm, tid,       y0, G2);
        stage1_col<true >(sp, sm, tid + NTH, y0, G2);
    }
    __syncthreads();

    #pragma unroll
    for (int t = 0; t < 2; ++t) {
        const int gy = y0 + (t ? row1 : row0);
        const int xc = (t ? l1 : l0) << 3;
        u64 acc[8];
        hblur(t ? smr1 : smr0, G2, acc);
        float res[8];
        #pragma unroll
        for (int o = 0; o < 8; ++o) {
            float smn, sE2;
            unpack2(acc[o], smn, sE2);
            const float sv  = fmaxf(fmaf(-smn, smn, sE2), 1e-6f);
            const float rqs = frsq_ap(sv);                  // MUFU.RSQ
            const float numer = fmaf(sv, rqs, 1e-5f);       // sqrt(sv)+eps
            res[o] = fmaf(normed[t * 8 + o], numer, smn);
        }
        *reinterpret_cast<float4*>(op + gy * WIDTH + xc) =
            make_float4(res[0], res[1], res[2], res[3]);
        *reinterpret_cast<float4*>(op + gy * WIDTH + xc + 4) =
            make_float4(res[4], res[5], res[6], res[7]);
    }
}

extern "C" void kernel_launch(void* const* d_in, const int* in_sizes, int n_in,
                              void* d_out, int out_size) {
    const float* content = (const float*)d_in[0];
    const float* style   = (const float*)d_in[1];
    float*       out     = (float*)d_out;

    const int planes = in_sizes[0] / (WIDTH * HEIGHT);   // 4*64 = 256

    cudaFuncSetAttribute(adain_local_kernel,
                         cudaFuncAttributeMaxDynamicSharedMemorySize, SMEM_BYTES);

    dim3 grid(HEIGHT / TH, planes);
    adain_local_kernel<<<grid, NTH, SMEM_BYTES>>>(content, style, out);
}